// round 4
// baseline (speedup 1.0000x reference)
#include <cuda_runtime.h>
#include <math.h>

#define TPB 128
#define RPB 128
#define NC 99
#define NBLK_MAX 1024

// smem: s_dec (RPB*NC f) + s_hist (202 i) + s_red (8 f) + s_mm (20 u)
#define SMEM_BYTES (RPB*NC*4 + 202*4 + 8*4 + 20*4)

// ---------------- persistent scratch (written each launch; replay-safe) ----------------
__device__ unsigned g_cnt = 0;                    // barrier counter (self-resetting)
__device__ unsigned g_gen = 0;                    // barrier generation (monotonic)
__device__ unsigned g_bmm[NBLK_MAX][20];          // per-block minmax keys
__device__ double   g_bpart[NBLK_MAX][2];         // per-block (mse, ce) partials
__device__ int      g_hist[202];                  // zeroed by block 0 in phase A

// monotonic float <-> uint key
__device__ __forceinline__ unsigned fkey(float f) {
    unsigned u = __float_as_uint(f);
    return (u & 0x80000000u) ? ~u : (u | 0x80000000u);
}
__device__ __forceinline__ float kinv(unsigned k) {
    return __uint_as_float((k & 0x80000000u) ? (k & 0x7fffffffu) : ~k);
}

// generation-based grid barrier: counter resets to 0 each use, gen grows monotonically
__device__ __forceinline__ void gbar(unsigned nblk) {
    __syncthreads();
    if (threadIdx.x == 0) {
        __threadfence();
        unsigned snap = *((volatile unsigned*)&g_gen);
        unsigned tick = atomicAdd(&g_cnt, 1);
        if (tick == nblk - 1) {
            atomicExch(&g_cnt, 0);
            __threadfence();
            atomicAdd(&g_gen, 1);
        } else {
            while (*((volatile unsigned*)&g_gen) == snap) __nanosleep(64);
        }
        __threadfence();
    }
    __syncthreads();
}

__global__ void __launch_bounds__(TPB, 4) k_fused(const float* __restrict__ enc,
                                                  const float* __restrict__ dec,
                                                  const float* __restrict__ tru,
                                                  float* __restrict__ out,
                                                  int B, int nblk) {
    extern __shared__ float sm[];
    float*    s_dec  = sm;
    int*      s_hist = (int*)(s_dec + RPB * NC);
    float*    s_red  = (float*)(s_hist + 202);
    unsigned* s_mm   = (unsigned*)(s_red + 8);

    const int t   = threadIdx.x;
    const int blk = blockIdx.x;
    const int NT  = B / RPB;

    // block 0 zeroes the global histogram; ordered before any phase-B atomics by barrier 1
    if (blk == 0) for (int i = t; i < 202; i += TPB) g_hist[i] = 0;

    // =========================== PHASE A ===========================
    float mse = 0.0f, dot = 0.0f, lse = 0.0f;
    float mn[10], mx[10];
#pragma unroll
    for (int f = 0; f < 10; f++) { mn[f] = INFINITY; mx[f] = -INFINITY; }

    const int bs[8] = {1, 8, 24, 31, 45, 51, 53, 58};
    const int be[8] = {8, 24, 31, 45, 51, 53, 55, 99};

    for (int tile = blk; tile < NT; tile += nblk) {
        __syncthreads();   // protect s_dec from previous tile's lse readers

        // stream dec (stash) + tru (consume): mse on cont cols, dot on categorical
        const size_t base = (size_t)tile * (RPB * NC);
        const float4* dsrc = (const float4*)(dec + base);
        const float4* tsrc = (const float4*)(tru + base);
        float4* sdec4 = (float4*)s_dec;
        int c = (4 * t) % 99;
        for (int i = t; i < (RPB * NC) / 4; i += TPB) {
            float4 d4 = dsrc[i];
            sdec4[i] = d4;
            float4 t4 = tsrc[i];
            float dv[4] = {d4.x, d4.y, d4.z, d4.w};
            float tv[4] = {t4.x, t4.y, t4.z, t4.w};
#pragma unroll
            for (int j = 0; j < 4; j++) {
                int cc = c + j; if (cc >= 99) cc -= 99;
                bool cont = (cc == 0) | ((unsigned)(cc - 55) < 3u);
                if (cont) { float df = dv[j] - tv[j]; mse += df * df; }
                else      dot = fmaf(tv[j], dv[j], dot);
            }
            c += 17; if (c >= 99) c -= 99;   // (4*TPB) % 99 == 17
        }
        __syncthreads();

        // per-row log-sum-exp (row t of tile); stride-99 LDS is conflict-free (gcd(99,32)=1)
        const float* dr = &s_dec[t * NC];
#pragma unroll
        for (int b = 0; b < 8; b++) {
            float m = -INFINITY;
            for (int cix = bs[b]; cix < be[b]; cix++) m = fmaxf(m, dr[cix]);
            float sum = 0.0f;
            for (int cix = bs[b]; cix < be[b]; cix++) sum += __expf(dr[cix] - m);
            lse += m + __logf(sum);
        }

        // enc min/max for this row (enc lands in L2 for phase-B re-read)
        {
            const float4* ep = (const float4*)(enc + ((size_t)tile * RPB + t) * 12);
            float4 a = ep[0], b4 = ep[1], c4 = ep[2];
            float fv[10] = {a.x, a.y, a.z, a.w, b4.x, b4.y, b4.z, b4.w, c4.x, c4.y};
#pragma unroll
            for (int f = 0; f < 10; f++) { mn[f] = fminf(mn[f], fv[f]); mx[f] = fmaxf(mx[f], fv[f]); }
        }
    }

    // block-reduce minmax -> g_bmm[blk]
    if (t < 10) s_mm[t] = 0xFFFFFFFFu; else if (t < 20) s_mm[t] = 0u;
    // block-reduce mse/ce partials
    float ce = lse - dot;
#pragma unroll
    for (int o = 16; o > 0; o >>= 1) {
        mse += __shfl_xor_sync(0xffffffffu, mse, o);
        ce  += __shfl_xor_sync(0xffffffffu, ce,  o);
#pragma unroll
        for (int f = 0; f < 10; f++) {
            mn[f] = fminf(mn[f], __shfl_xor_sync(0xffffffffu, mn[f], o));
            mx[f] = fmaxf(mx[f], __shfl_xor_sync(0xffffffffu, mx[f], o));
        }
    }
    __syncthreads();
    int w = t >> 5, lane = t & 31;
    if (lane == 0) {
        s_red[w] = mse; s_red[4 + w] = ce;
#pragma unroll
        for (int f = 0; f < 10; f++) {
            atomicMin(&s_mm[f],      fkey(mn[f]));
            atomicMax(&s_mm[10 + f], fkey(mx[f]));
        }
    }
    __syncthreads();
    if (t == 0) {
        g_bpart[blk][0] = (double)(s_red[0] + s_red[1] + s_red[2] + s_red[3]);
        g_bpart[blk][1] = (double)(s_red[4] + s_red[5] + s_red[6] + s_red[7]);
    }
    if (t < 20) g_bmm[blk][t] = s_mm[t];
    __threadfence();

    gbar(nblk);   // ======================= BARRIER 1 =======================

    // every block reduces the global minmax from per-block keys (L2-resident)
    if (t < 10) s_mm[t] = 0xFFFFFFFFu; else if (t < 20) s_mm[t] = 0u;
    for (int i = t; i < 202; i += TPB) s_hist[i] = 0;
    __syncthreads();
    if (t < 120) {
        int f = t % 20;                  // f in [0,10): min slot f; f in [10,20): max slot f
        unsigned acc = (f < 10) ? 0xFFFFFFFFu : 0u;
        for (int b = t / 20; b < nblk; b += 6) {
            unsigned v = g_bmm[b][f];
            acc = (f < 10) ? min(acc, v) : max(acc, v);
        }
        if (f < 10) atomicMin(&s_mm[f], acc);
        else        atomicMax(&s_mm[f], acc);   // FIX: was s_mm[10+f] (OOB; max slots stayed 0)
    }
    __syncthreads();

    float mnv[10], wv[10];
#pragma unroll
    for (int f = 0; f < 10; f++) {
        mnv[f] = kinv(s_mm[f]);
        float mxv = kinv(s_mm[10 + f]);
        wv[f] = fmaxf(__fsub_rn(mxv, mnv[f]), 1e-12f);
    }

    // =========================== PHASE B: histograms ===========================
    for (int tile = blk; tile < NT; tile += nblk) {
        const float4* ep = (const float4*)(enc + ((size_t)tile * RPB + t) * 12);
        float4 a = ep[0], b4 = ep[1], c4 = ep[2];
        float fv[10] = {a.x, a.y, a.z, a.w, b4.x, b4.y, b4.z, b4.w, c4.x, c4.y};
        float sex = c4.w;
        int sel = (sex == 0.0f) ? 0 : ((sex == 1.0f) ? 1 : -1);
        if (sel >= 0) {
            atomicAdd(&s_hist[200 + sel], 1);
#pragma unroll
            for (int f = 0; f < 10; f++) {
                float u = __fmul_rn(__fdiv_rn(__fsub_rn(fv[f], mnv[f]), wv[f]), 10.0f);
                int bi = (int)floorf(u);
                bi = bi < 0 ? 0 : (bi > 9 ? 9 : bi);
                atomicAdd(&s_hist[sel * 100 + f * 10 + bi], 1);
            }
        }
    }
    __syncthreads();
    for (int i = t; i < 202; i += TPB) {
        int v = s_hist[i];
        if (v) atomicAdd(&g_hist[i], v);
    }
    __threadfence();

    gbar(nblk);   // ======================= BARRIER 2 =======================

    if (blk != 0) return;

    // =========================== FINALIZE (block 0) ===========================
    double pm = 0.0, pc = 0.0;
    for (int b = t; b < nblk; b += TPB) { pm += g_bpart[b][0]; pc += g_bpart[b][1]; }
    double* sd = (double*)s_dec;
    sd[t] = pm; sd[TPB + t] = pc;
    __syncthreads();
    for (int s = TPB / 2; s > 0; s >>= 1) {
        if (t < s) { sd[t] += sd[t + s]; sd[TPB + t] += sd[TPB + t + s]; }
        __syncthreads();
    }

    if (t < 32) {
        float mc = fmaxf((float)g_hist[200], 1.0f);
        float fc = fmaxf((float)g_hist[201], 1.0f);
        float kl = 0.0f;
        for (int i = t; i < 100; i += 32) {
            float p = __fdiv_rn((float)g_hist[i],       mc);
            float q = __fdiv_rn((float)g_hist[100 + i], fc);
            if (p > 0.0f && q > 0.0f) kl += __fmul_rn(p, logf(__fdiv_rn(p, q)));
        }
#pragma unroll
        for (int o = 16; o > 0; o >>= 1) kl += __shfl_xor_sync(0xffffffffu, kl, o);
        if (t == 0) {
            double invB = 1.0 / (double)B;
            float msev = (float)(sd[0] * invB);
            float cev  = (float)(sd[TPB] * invB);
            out[0] = 0.5f * (msev + cev) + 0.5f * kl;   // alpha = 0.5
            out[1] = msev;
            out[2] = cev;
            out[3] = 0.5f * kl;
        }
    }
}

// ---------------- launch ----------------
extern "C" void kernel_launch(void* const* d_in, const int* in_sizes, int n_in,
                              void* d_out, int out_size) {
    const float* enc = (const float*)d_in[0];   // [B,12]
    const float* dec = (const float*)d_in[1];   // [B,99]
    const float* tru = (const float*)d_in[2];   // [B,99]
    int B = in_sizes[1] / NC;

    cudaFuncSetAttribute(k_fused, cudaFuncAttributeMaxDynamicSharedMemorySize, SMEM_BYTES);

    int dev = 0; cudaGetDevice(&dev);
    int nsm = 0; cudaDeviceGetAttribute(&nsm, cudaDevAttrMultiProcessorCount, dev);
    int occ = 0;
    cudaOccupancyMaxActiveBlocksPerMultiprocessor(&occ, k_fused, TPB, SMEM_BYTES);
    if (occ < 1) occ = 1;
    int nblk = occ * nsm;
    if (nblk > NBLK_MAX) nblk = NBLK_MAX;
    int NT = B / RPB;
    if (nblk > NT) nblk = NT;

    k_fused<<<nblk, TPB, SMEM_BYTES>>>(enc, dec, tru, (float*)d_out, B, nblk);
}